// round 17
// baseline (speedup 1.0000x reference)
#include <cuda_runtime.h>

// ComplexityAnalyzer: per-image 64-bin histogram + L1 normalize + 64->32->128 MLP.
// Inputs: grad_map [B*512*512] f32, W1 [32*64], b1 [32], W2 [128*32], b2 [128].
// Output: [B*128] f32.
//
// R17: persistent 148-CTA kernel with dynamic ticket stealing. The shared-ATOMS
// wall (~4.8 lane-ops/cyc/SM, needs 32 warps) scales only with active SMs;
// static 148-CTA splits lost ~30%/SM (suspect: imbalance / dual-bank SEL).
// Tickets are image-aligned 8192-float4 chunks -> inner loop is EXACTLY R2's
// (one hist bank, static trip, unroll 4). Ticket counter double-buffer
// prefetched; image-change flush + done-counter protocol (proven in R12);
// finishing CTA runs the MLP; counters self-reset for graph replay.

#define THREADS 1024
#define WARPS   32
#define NPAD    66            // 65 live bins (0..63 + catch 64), padded
#define TICKET_ITERS 8        // 8 x 1024 float4 per ticket = 1/8 image
#define TPI     8             // tickets per image
#define MAX_IMG 256

__device__ unsigned int g_hist[MAX_IMG * 64];   // zero-init; self-cleaning
__device__ unsigned int g_done[MAX_IMG];        // zero-init; self-cleaning
__device__ unsigned int g_ticket;               // zero-init; self-resetting
__device__ unsigned int g_exit;                 // zero-init; self-resetting

__global__ __launch_bounds__(THREADS, 1)
void ca_hist_mlp_kernel(const float* __restrict__ grad,
                        const float* __restrict__ W1, const float* __restrict__ b1,
                        const float* __restrict__ W2, const float* __restrict__ b2,
                        float* __restrict__ out, int totalTickets)
{
    __shared__ unsigned int hist[WARPS * NPAD];   // 8448 B
    __shared__ unsigned int sh_nx[2];
    __shared__ float fh[64];
    __shared__ float hmid[32];
    __shared__ float inv_s;
    __shared__ int sh_do;

    const int tid = threadIdx.x;
    const int wid = tid >> 5;

    // Zero hist; pull first ticket.
    #pragma unroll
    for (int i = tid; i < WARPS * NPAD; i += THREADS)
        hist[i] = 0u;
    if (tid == 0) sh_nx[0] = atomicAdd(&g_ticket, 1u);
    __syncthreads();

    unsigned int* myh = hist + wid * NPAD;
    const float scale = 64.0f / 255.0f;
    const float magic = 8388608.0f;  // 2^23

    int par = 0;
    int t = (int)sh_nx[0];
    int curImg = -1;
    unsigned pending = 0;

    while (t < totalTickets) {
        // Prefetch next ticket into the other buffer (latency hidden by work).
        if (tid == 0) sh_nx[par ^ 1] = atomicAdd(&g_ticket, 1u);

        const int img = t >> 3;
        if (img != curImg) {
            if (curImg >= 0) {
                // ---- flush curImg ----
                __syncthreads();
                if (tid < 64) {
                    unsigned s = 0;
                    #pragma unroll
                    for (int w = 0; w < WARPS; ++w)
                        s += hist[w * NPAD + tid];
                    if (tid == 63) {
                        #pragma unroll
                        for (int w = 0; w < WARPS; ++w)
                            s += hist[w * NPAD + 64];
                    }
                    if (s) atomicAdd(&g_hist[curImg * 64 + tid], s);
                    __threadfence();
                }
                __syncthreads();
                if (tid == 0) {
                    unsigned old = atomicAdd(&g_done[curImg], pending);
                    sh_do = (old + pending == (unsigned)TPI);
                }
                #pragma unroll
                for (int i = tid; i < WARPS * NPAD; i += THREADS)
                    hist[i] = 0u;
                __syncthreads();
                if (sh_do) {
                    if (tid < 64) {
                        __threadfence();
                        fh[tid] = (float)atomicAdd(&g_hist[curImg * 64 + tid], 0u);
                    }
                    __syncthreads();
                    if (tid < 32) {
                        float s2 = fh[tid] + fh[tid + 32];
                        #pragma unroll
                        for (int off = 16; off > 0; off >>= 1)
                            s2 += __shfl_down_sync(0xFFFFFFFFu, s2, off);
                        if (tid == 0) inv_s = 1.0f / fmaxf(s2, 1e-12f);
                    }
                    __syncthreads();
                    if (tid < 64) fh[tid] *= inv_s;
                    __syncthreads();
                    if (tid < 32) {
                        float acc = b1[tid];
                        const float* w = W1 + tid * 64;
                        #pragma unroll
                        for (int b = 0; b < 64; ++b) acc = fmaf(fh[b], w[b], acc);
                        hmid[tid] = fmaxf(acc, 0.0f);
                    }
                    __syncthreads();
                    if (tid < 128) {
                        float acc = b2[tid];
                        const float* w = W2 + tid * 32;
                        #pragma unroll
                        for (int j = 0; j < 32; ++j) acc = fmaf(hmid[j], w[j], acc);
                        out[curImg * 128 + tid] = acc;
                    }
                    if (tid < 64) atomicExch(&g_hist[curImg * 64 + tid], 0u);
                    if (tid == 0) atomicExch(&g_done[curImg], 0u);
                    __syncthreads();
                }
            }
            curImg = img;
            pending = 0;
        }

        // ---- process ticket t: R2's exact inner loop, 8 static iters ----
        {
            const float4* p = (const float4*)grad + ((size_t)t << 13) + tid;
            #pragma unroll 4
            for (int it = 0; it < TICKET_ITERS; ++it) {
                float4 v = __ldg(&p[it * THREADS]);
                float q0, q1, q2, q3;
                asm("fma.rz.f32 %0, %1, %2, %3;" : "=f"(q0) : "f"(v.x), "f"(scale), "f"(magic));
                asm("fma.rz.f32 %0, %1, %2, %3;" : "=f"(q1) : "f"(v.y), "f"(scale), "f"(magic));
                asm("fma.rz.f32 %0, %1, %2, %3;" : "=f"(q2) : "f"(v.z), "f"(scale), "f"(magic));
                asm("fma.rz.f32 %0, %1, %2, %3;" : "=f"(q3) : "f"(v.w), "f"(scale), "f"(magic));
                atomicAdd(&myh[min(__float_as_uint(q0) & 0x7Fu, 64u)], 1u);
                atomicAdd(&myh[min(__float_as_uint(q1) & 0x7Fu, 64u)], 1u);
                atomicAdd(&myh[min(__float_as_uint(q2) & 0x7Fu, 64u)], 1u);
                atomicAdd(&myh[min(__float_as_uint(q3) & 0x7Fu, 64u)], 1u);
            }
        }
        pending++;

        __syncthreads();              // next-ticket buffer ready; separates buffers
        par ^= 1;
        t = (int)sh_nx[par];
    }

    // ---- final flush ----
    if (curImg >= 0) {
        __syncthreads();
        if (tid < 64) {
            unsigned s = 0;
            #pragma unroll
            for (int w = 0; w < WARPS; ++w)
                s += hist[w * NPAD + tid];
            if (tid == 63) {
                #pragma unroll
                for (int w = 0; w < WARPS; ++w)
                    s += hist[w * NPAD + 64];
            }
            if (s) atomicAdd(&g_hist[curImg * 64 + tid], s);
            __threadfence();
        }
        __syncthreads();
        if (tid == 0) {
            unsigned old = atomicAdd(&g_done[curImg], pending);
            sh_do = (old + pending == (unsigned)TPI);
        }
        __syncthreads();
        if (sh_do) {
            if (tid < 64) {
                __threadfence();
                fh[tid] = (float)atomicAdd(&g_hist[curImg * 64 + tid], 0u);
            }
            __syncthreads();
            if (tid < 32) {
                float s2 = fh[tid] + fh[tid + 32];
                #pragma unroll
                for (int off = 16; off > 0; off >>= 1)
                    s2 += __shfl_down_sync(0xFFFFFFFFu, s2, off);
                if (tid == 0) inv_s = 1.0f / fmaxf(s2, 1e-12f);
            }
            __syncthreads();
            if (tid < 64) fh[tid] *= inv_s;
            __syncthreads();
            if (tid < 32) {
                float acc = b1[tid];
                const float* w = W1 + tid * 64;
                #pragma unroll
                for (int b = 0; b < 64; ++b) acc = fmaf(fh[b], w[b], acc);
                hmid[tid] = fmaxf(acc, 0.0f);
            }
            __syncthreads();
            if (tid < 128) {
                float acc = b2[tid];
                const float* w = W2 + tid * 32;
                #pragma unroll
                for (int j = 0; j < 32; ++j) acc = fmaf(hmid[j], w[j], acc);
                out[curImg * 128 + tid] = acc;
            }
            if (tid < 64) atomicExch(&g_hist[curImg * 64 + tid], 0u);
            if (tid == 0) atomicExch(&g_done[curImg], 0u);
            __syncthreads();
        }
    }

    // ---- exit protocol: last exiter resets ticket/exit counters ----
    __syncthreads();
    if (tid == 0) {
        __threadfence();
        unsigned e = atomicAdd(&g_exit, 1u);
        if (e == gridDim.x - 1) {
            atomicExch(&g_ticket, 0u);
            atomicExch(&g_exit, 0u);
        }
    }
}

extern "C" void kernel_launch(void* const* d_in, const int* in_sizes, int n_in,
                              void* d_out, int out_size) {
    const float* grad = (const float*)d_in[0];
    const float* W1   = (const float*)d_in[1];
    const float* b1   = (const float*)d_in[2];
    const float* W2   = (const float*)d_in[3];
    const float* b2   = (const float*)d_in[4];
    float* out = (float*)d_out;

    int totalTickets = in_sizes[0] / (512 * 512) * TPI;   // 8 per image
    int nCta = totalTickets < 148 ? totalTickets : 148;
    ca_hist_mlp_kernel<<<nCta, THREADS>>>(grad, W1, b1, W2, b2, out, totalTickets);
}